// round 16
// baseline (speedup 1.0000x reference)
#include <cuda_runtime.h>

typedef unsigned long long u64;
typedef unsigned int u32;

// ---- packed f32x2 helpers (PTX-only; ptxas never auto-fuses) ----
__device__ __forceinline__ u64 pack2(float lo, float hi) {
    u64 r; asm("mov.b64 %0, {%1, %2};" : "=l"(r) : "f"(lo), "f"(hi)); return r;
}
__device__ __forceinline__ void unpack2(u64 v, float& lo, float& hi) {
    asm("mov.b64 {%0, %1}, %2;" : "=f"(lo), "=f"(hi) : "l"(v));
}
__device__ __forceinline__ u64 fma2(u64 a, u64 b, u64 c) {
    u64 d; asm("fma.rn.f32x2 %0, %1, %2, %3;" : "=l"(d) : "l"(a), "l"(b), "l"(c)); return d;
}
// one LDS.128 (broadcast): 4 consecutive floats as two f32x2 pairs
__device__ __forceinline__ void lds2(u32 addr, u64& p0, u64& p1) {
    asm volatile("ld.shared.v2.u64 {%0, %1}, [%2];" : "=l"(p0), "=l"(p1) : "r"(addr));
}
__device__ __forceinline__ u64 lds64(u32 addr) {
    u64 v; asm volatile("ld.shared.u64 %0, [%1];" : "=l"(v) : "r"(addr)); return v;
}
__device__ __forceinline__ u32 smem_u32(const void* p) {
    u32 a; asm("{ .reg .u64 t; cvta.to.shared.u64 t, %1; cvt.u32.u64 %0, t; }" : "=r"(a) : "l"(p));
    return a;
}

// ---- MUFU primitives ----
__device__ __forceinline__ float ex2f(float x) { float r; asm("ex2.approx.f32 %0, %1;" : "=f"(r) : "f"(x)); return r; }
__device__ __forceinline__ float rcpf(float x) { float r; asm("rcp.approx.f32 %0, %1;" : "=f"(r) : "f"(x)); return r; }
__device__ __forceinline__ float tanhf_(float x) { return fmaf(-2.0f, rcpf(1.0f + ex2f(2.8853900817779268f * x)), 1.0f); }

#define TSTEPS 512
#define WARPS_PER_CTA 4
#define ROWS_PER_WARP 2

// One warp per TWO batch rows, alternate A/B steps (R14 committed structure).
// Gates i,f,g weights in 96 registers; gate-o weights streamed per step from a
// 4KB SMEM table (16 LDS.64/row-step, ~32 crossbar cyc) -> frees ~32 registers
// of scheduling slack so ptxas can pipeline the h-loads (occupancy unchanged:
// 3 CTAs/SM). Activation scales pre-folded; ping-pong h; 1 syncwarp/row-step.
__global__ void __launch_bounds__(32 * WARPS_PER_CTA, 3)
lstm_kernel(const float* __restrict__ x,
            const float* __restrict__ W_ih,
            const float* __restrict__ W_hh,
            const float* __restrict__ b_ih,
            const float* __restrict__ b_hh,
            const float* __restrict__ W_fc,
            const float* __restrict__ b_fc,
            float* __restrict__ out, int B)
{
    // o-gate weight table: wsm[j*32 + unit] = {SG3*W_o[unit][2j], SG3*W_o[unit][2j+1]}
    __shared__ __align__(16) u64   wsm[16 * 32];
    // hbuf[phase][warp][row][unit] : phase stride 1024B, row stride 128B
    __shared__ __align__(16) float hbuf[2][WARPS_PER_CTA][ROWS_PER_WARP][32];
    __shared__ __align__(16) float xsm[WARPS_PER_CTA][ROWS_PER_WARP][32];

    const int wl   = threadIdx.x >> 5;
    const int lane = threadIdx.x & 31;
    const int bA   = (blockIdx.x * WARPS_PER_CTA + wl) * ROWS_PER_WARP;
    const int bB   = bA + 1;

    // sigmoid(a)=rcp(1+ex2(-log2e*a)); tanh(a)=fma(-2, rcp(1+ex2(2*log2e*a)), 1)
    const float SG0 = -1.4426950408889634f;  // i
    const float SG1 = -1.4426950408889634f;  // f
    const float SG2 =  2.8853900817779268f;  // g (tanh)
    const float SG3 = -1.4426950408889634f;  // o

    // ---- fill o-gate table (each warp: 4 j values) ----
#pragma unroll
    for (int q = 0; q < 4; q++) {
        const int j = wl * 4 + q;
        const float* ro = W_hh + (96 + lane) * 32 + 2 * j;
        wsm[j * 32 + lane] = pack2(SG3 * ro[0], SG3 * ro[1]);
    }

    // ---- i,f,g weights in registers: 48 u64 = 96 regs ----
    u64 w0[16], w1[16], w2[16];
#pragma unroll
    for (int q = 0; q < 16; q++) {
        const float* r0 = W_hh + (lane)      * 32 + 2 * q;
        const float* r1 = W_hh + (32 + lane) * 32 + 2 * q;
        const float* r2 = W_hh + (64 + lane) * 32 + 2 * q;
        w0[q] = pack2(SG0 * r0[0], SG0 * r0[1]);
        w1[q] = pack2(SG1 * r1[0], SG1 * r1[1]);
        w2[q] = pack2(SG2 * r2[0], SG2 * r2[1]);
    }
    const float wih0 = SG0 * W_ih[lane],      bia0 = SG0 * (b_ih[lane]      + b_hh[lane]);
    const float wih1 = SG1 * W_ih[32 + lane], bia1 = SG1 * (b_ih[32 + lane] + b_hh[32 + lane]);
    const float wih2 = SG2 * W_ih[64 + lane], bia2 = SG2 * (b_ih[64 + lane] + b_hh[64 + lane]);
    const float wih3 = SG3 * W_ih[96 + lane], bia3 = SG3 * (b_ih[96 + lane] + b_hh[96 + lane]);

    float hA = 0.f, cA = 0.f, hB = 0.f, cB = 0.f;
    hbuf[0][wl][0][lane] = 0.0f;
    hbuf[0][wl][1][lane] = 0.0f;
    __syncthreads();                 // weight table + h init visible
    if (bA >= B) return;

    // base smem addrs; offsets: +1024 -> phase 1, +128 -> row B, +lane*4 slot
    const u32 hb = smem_u32(&hbuf[0][wl][0][0]);
    const u32 wo = smem_u32(&wsm[0]) + lane * 8;   // this lane's o-weight column
    const float* xspA = &xsm[wl][0][0];
    const float* xspB = &xsm[wl][1][0];
    const float* xbA  = x + (size_t)bA * TSTEPS;
    const float* xbB  = x + (size_t)bB * TSTEPS;

// one row-step: RD/WR u32 smem byte addrs (phase/row folded by caller)
#define STEP(XV, RD, WR, HS, CS)                                               \
    {                                                                          \
        const float xv = (XV);                                                 \
        u64 a0 = 0ull, a1 = 0ull, a2 = 0ull, a3 = 0ull;                        \
        _Pragma("unroll")                                                      \
        for (int m = 0; m < 8; m++) {                                          \
            u64 pA_, pB_;                                                      \
            lds2((RD) + m * 16, pA_, pB_);                                     \
            const u64 wo0 = lds64(wo + (2 * m)     * 256);                     \
            const u64 wo1 = lds64(wo + (2 * m + 1) * 256);                     \
            a0 = fma2(w0[2 * m],     pA_, a0);                                 \
            a1 = fma2(w1[2 * m],     pA_, a1);                                 \
            a2 = fma2(w2[2 * m],     pA_, a2);                                 \
            a3 = fma2(wo0,           pA_, a3);                                 \
            a0 = fma2(w0[2 * m + 1], pB_, a0);                                 \
            a1 = fma2(w1[2 * m + 1], pB_, a1);                                 \
            a2 = fma2(w2[2 * m + 1], pB_, a2);                                 \
            a3 = fma2(wo1,           pB_, a3);                                 \
        }                                                                      \
        float l0, u0_, l1, u1_, l2, u2_, l3, u3_;                              \
        unpack2(a0, l0, u0_);                                                  \
        unpack2(a1, l1, u1_);                                                  \
        unpack2(a2, l2, u2_);                                                  \
        unpack2(a3, l3, u3_);                                                  \
        const float s0 = fmaf(xv, wih0, bia0) + (l0 + u0_);                    \
        const float s1 = fmaf(xv, wih1, bia1) + (l1 + u1_);                    \
        const float s2 = fmaf(xv, wih2, bia2) + (l2 + u2_);                    \
        const float s3 = fmaf(xv, wih3, bia3) + (l3 + u3_);                    \
        const float ig = rcpf(1.0f + ex2f(s0));                                \
        const float fg = rcpf(1.0f + ex2f(s1));                                \
        const float gg = fmaf(-2.0f, rcpf(1.0f + ex2f(s2)), 1.0f);             \
        const float og = rcpf(1.0f + ex2f(s3));                                \
        (CS) = fmaf(fg, (CS), ig * gg);                                        \
        (HS) = og * tanhf_((CS));                                              \
        asm volatile("st.shared.f32 [%0], %1;"                                 \
                     :: "r"((WR) + lane * 4), "f"(HS) : "memory");             \
        __syncwarp();                                                          \
    }

#pragma unroll 1
    for (int tc = 0; tc < TSTEPS; tc += 32) {
        xsm[wl][0][lane] = xbA[tc + lane];   // coalesced 128B per warp
        xsm[wl][1][lane] = xbB[tc + lane];
        __syncwarp();

#pragma unroll 1
        for (int tt = 0; tt < 32; tt += 2) {
            // phase 0 -> 1
            STEP(xspA[tt],     hb,              hb + 1024,       hA, cA)
            STEP(xspB[tt],     hb + 128,        hb + 1024 + 128, hB, cB)
            // phase 1 -> 0
            STEP(xspA[tt + 1], hb + 1024,       hb,              hA, cA)
            STEP(xspB[tt + 1], hb + 1024 + 128, hb + 128,        hB, cB)
        }
    }
#undef STEP

    // ---- final head: out[b] = dot(h, W_fc) + b_fc ----
    const float wfc = W_fc[lane];
    float pA = hA * wfc, pB = hB * wfc;
#pragma unroll
    for (int off = 16; off; off >>= 1) {
        pA += __shfl_xor_sync(0xffffffffu, pA, off);
        pB += __shfl_xor_sync(0xffffffffu, pB, off);
    }
    if (lane == 0) {
        out[bA] = pA + b_fc[0];
        if (bB < B) out[bB] = pB + b_fc[0];
    }
}

extern "C" void kernel_launch(void* const* d_in, const int* in_sizes, int n_in,
                              void* d_out, int out_size)
{
    const float* x    = (const float*)d_in[0];
    const float* W_ih = (const float*)d_in[1];
    const float* W_hh = (const float*)d_in[2];
    const float* b_ih = (const float*)d_in[3];
    const float* b_hh = (const float*)d_in[4];
    const float* W_fc = (const float*)d_in[5];
    const float* b_fc = (const float*)d_in[6];
    float* out = (float*)d_out;

    int B = in_sizes[0] / TSTEPS;  // x is [B, 512, 1]
    int rows_per_cta = WARPS_PER_CTA * ROWS_PER_WARP;
    int blocks = (B + rows_per_cta - 1) / rows_per_cta;
    lstm_kernel<<<blocks, 32 * WARPS_PER_CTA>>>(x, W_ih, W_hh, b_ih, b_hh, W_fc, b_fc, out, B);
}

// round 17
// speedup vs baseline: 1.1970x; 1.1970x over previous
#include <cuda_runtime.h>

typedef unsigned long long u64;
typedef unsigned int u32;

// ---- packed f32x2 helpers (PTX-only; ptxas never auto-fuses) ----
__device__ __forceinline__ u64 pack2(float lo, float hi) {
    u64 r; asm("mov.b64 %0, {%1, %2};" : "=l"(r) : "f"(lo), "f"(hi)); return r;
}
__device__ __forceinline__ void unpack2(u64 v, float& lo, float& hi) {
    asm("mov.b64 {%0, %1}, %2;" : "=f"(lo), "=f"(hi) : "l"(v));
}
__device__ __forceinline__ u64 fma2(u64 a, u64 b, u64 c) {
    u64 d; asm("fma.rn.f32x2 %0, %1, %2, %3;" : "=l"(d) : "l"(a), "l"(b), "l"(c)); return d;
}
// one LDS.128 (broadcast): 4 consecutive floats as two f32x2 pairs
__device__ __forceinline__ void lds2(u32 addr, u64& p0, u64& p1) {
    asm volatile("ld.shared.v2.u64 {%0, %1}, [%2];" : "=l"(p0), "=l"(p1) : "r"(addr));
}
__device__ __forceinline__ u32 smem_u32(const void* p) {
    u32 a; asm("{ .reg .u64 t; cvta.to.shared.u64 t, %1; cvt.u32.u64 %0, t; }" : "=r"(a) : "l"(p));
    return a;
}

// ---- MUFU primitives ----
__device__ __forceinline__ float ex2f(float x)   { float r; asm("ex2.approx.f32 %0, %1;"  : "=f"(r) : "f"(x)); return r; }
__device__ __forceinline__ float rcpf(float x)   { float r; asm("rcp.approx.f32 %0, %1;"  : "=f"(r) : "f"(x)); return r; }
__device__ __forceinline__ float tanhap(float x) { float r; asm("tanh.approx.f32 %0, %1;" : "=f"(r) : "f"(x)); return r; }
// accurate tanh for the c-path (ex2+rcp, ~fp32 accurate)
__device__ __forceinline__ float tanhf_(float x) { return fmaf(-2.0f, rcpf(1.0f + ex2f(2.8853900817779268f * x)), 1.0f); }

#define TSTEPS 512
#define WARPS_PER_CTA 4
#define ROWS_PER_WARP 2

// One warp per TWO batch rows, alternate A/B steps (R14 committed structure).
// KEY CHANGE (R17): activations via HW MUFU.TANH —
//   sigmoid(a) = 0.5 + 0.5*tanh(a/2)  (1 MUFU; the /2 pre-folded into weights)
//   g-gate     = tanh.approx directly (1 MUFU)
//   tanh(c)    stays accurate ex2+rcp (2 MUFU)
// -> 6 MUFU per unit-update instead of 10; MUFU stops being the binding pipe.
__global__ void __launch_bounds__(32 * WARPS_PER_CTA, 3)
lstm_kernel(const float* __restrict__ x,
            const float* __restrict__ W_ih,
            const float* __restrict__ W_hh,
            const float* __restrict__ b_ih,
            const float* __restrict__ b_hh,
            const float* __restrict__ W_fc,
            const float* __restrict__ b_fc,
            float* __restrict__ out, int B)
{
    // hbuf[phase][warp][row][unit] : phase stride 1024B, row stride 128B
    __shared__ __align__(16) float hbuf[2][WARPS_PER_CTA][ROWS_PER_WARP][32];
    __shared__ __align__(16) float xsm[WARPS_PER_CTA][ROWS_PER_WARP][32];

    const int wl   = threadIdx.x >> 5;
    const int lane = threadIdx.x & 31;
    const int bA   = (blockIdx.x * WARPS_PER_CTA + wl) * ROWS_PER_WARP;
    const int bB   = bA + 1;
    if (bA >= B) return;

    // scale folding: sigmoid args halved (tanh half-angle), g-gate unscaled
    const float SG0 = 0.5f;   // i  (sigmoid via tanh)
    const float SG1 = 0.5f;   // f
    const float SG2 = 1.0f;   // g  (tanh directly)
    const float SG3 = 0.5f;   // o

    // ---- weights, gate-major k-pairs (scales folded): 64 u64 = 128 regs ----
    u64 w0[16], w1[16], w2[16], w3[16];
#pragma unroll
    for (int q = 0; q < 16; q++) {
        const float* r0 = W_hh + (lane)      * 32 + 2 * q;
        const float* r1 = W_hh + (32 + lane) * 32 + 2 * q;
        const float* r2 = W_hh + (64 + lane) * 32 + 2 * q;
        const float* r3 = W_hh + (96 + lane) * 32 + 2 * q;
        w0[q] = pack2(SG0 * r0[0], SG0 * r0[1]);
        w1[q] = pack2(SG1 * r1[0], SG1 * r1[1]);
        w2[q] = pack2(SG2 * r2[0], SG2 * r2[1]);
        w3[q] = pack2(SG3 * r3[0], SG3 * r3[1]);
    }
    const float wih0 = SG0 * W_ih[lane],      bia0 = SG0 * (b_ih[lane]      + b_hh[lane]);
    const float wih1 = SG1 * W_ih[32 + lane], bia1 = SG1 * (b_ih[32 + lane] + b_hh[32 + lane]);
    const float wih2 = SG2 * W_ih[64 + lane], bia2 = SG2 * (b_ih[64 + lane] + b_hh[64 + lane]);
    const float wih3 = SG3 * W_ih[96 + lane], bia3 = SG3 * (b_ih[96 + lane] + b_hh[96 + lane]);

    float hA = 0.f, cA = 0.f, hB = 0.f, cB = 0.f;
    hbuf[0][wl][0][lane] = 0.0f;
    hbuf[0][wl][1][lane] = 0.0f;

    // base smem addr for this warp's phase-0 row-A h buffer; offsets:
    //   +1024 -> phase 1, +128 -> row B, +lane*4 -> own slot
    const u32 hb = smem_u32(&hbuf[0][wl][0][0]);
    const float* xspA = &xsm[wl][0][0];
    const float* xspB = &xsm[wl][1][0];
    const float* xbA  = x + (size_t)bA * TSTEPS;
    const float* xbB  = x + (size_t)bB * TSTEPS;

// one row-step: RD/WR are u32 smem byte addrs (phase/row pre-folded)
#define STEP(XV, RD, WR, HS, CS)                                               \
    {                                                                          \
        const float xv = (XV);                                                 \
        u64 a0 = 0ull, a1 = 0ull, a2 = 0ull, a3 = 0ull;                        \
        _Pragma("unroll")                                                      \
        for (int m = 0; m < 8; m++) {                                          \
            u64 pA_, pB_;                                                      \
            lds2((RD) + m * 16, pA_, pB_);                                     \
            a0 = fma2(w0[2 * m],     pA_, a0);                                 \
            a1 = fma2(w1[2 * m],     pA_, a1);                                 \
            a2 = fma2(w2[2 * m],     pA_, a2);                                 \
            a3 = fma2(w3[2 * m],     pA_, a3);                                 \
            a0 = fma2(w0[2 * m + 1], pB_, a0);                                 \
            a1 = fma2(w1[2 * m + 1], pB_, a1);                                 \
            a2 = fma2(w2[2 * m + 1], pB_, a2);                                 \
            a3 = fma2(w3[2 * m + 1], pB_, a3);                                 \
        }                                                                      \
        float l0, u0_, l1, u1_, l2, u2_, l3, u3_;                              \
        unpack2(a0, l0, u0_);                                                  \
        unpack2(a1, l1, u1_);                                                  \
        unpack2(a2, l2, u2_);                                                  \
        unpack2(a3, l3, u3_);                                                  \
        const float s0 = fmaf(xv, wih0, bia0) + (l0 + u0_);                    \
        const float s1 = fmaf(xv, wih1, bia1) + (l1 + u1_);                    \
        const float s2 = fmaf(xv, wih2, bia2) + (l2 + u2_);                    \
        const float s3 = fmaf(xv, wih3, bia3) + (l3 + u3_);                    \
        const float ig = fmaf(0.5f, tanhap(s0), 0.5f);   /* sigmoid, 1 MUFU */ \
        const float fg = fmaf(0.5f, tanhap(s1), 0.5f);                         \
        const float gg = tanhap(s2);                     /* tanh,    1 MUFU */ \
        const float og = fmaf(0.5f, tanhap(s3), 0.5f);                         \
        (CS) = fmaf(fg, (CS), ig * gg);                                        \
        (HS) = og * tanhf_((CS));                        /* accurate c-path */ \
        asm volatile("st.shared.f32 [%0], %1;"                                 \
                     :: "r"((WR) + lane * 4), "f"(HS) : "memory");             \
        __syncwarp();                                                          \
    }

#pragma unroll 1
    for (int tc = 0; tc < TSTEPS; tc += 32) {
        xsm[wl][0][lane] = xbA[tc + lane];   // coalesced 128B per warp
        xsm[wl][1][lane] = xbB[tc + lane];
        __syncwarp();

#pragma unroll 1
        for (int tt = 0; tt < 32; tt += 2) {
            // phase 0 -> 1
            STEP(xspA[tt],     hb,              hb + 1024,       hA, cA)
            STEP(xspB[tt],     hb + 128,        hb + 1024 + 128, hB, cB)
            // phase 1 -> 0
            STEP(xspA[tt + 1], hb + 1024,       hb,              hA, cA)
            STEP(xspB[tt + 1], hb + 1024 + 128, hb + 128,        hB, cB)
        }
    }
#undef STEP

    // ---- final head: out[b] = dot(h, W_fc) + b_fc ----
    const float wfc = W_fc[lane];
    float pA = hA * wfc, pB = hB * wfc;
#pragma unroll
    for (int off = 16; off; off >>= 1) {
        pA += __shfl_xor_sync(0xffffffffu, pA, off);
        pB += __shfl_xor_sync(0xffffffffu, pB, off);
    }
    if (lane == 0) {
        out[bA] = pA + b_fc[0];
        if (bB < B) out[bB] = pB + b_fc[0];
    }
}

extern "C" void kernel_launch(void* const* d_in, const int* in_sizes, int n_in,
                              void* d_out, int out_size)
{
    const float* x    = (const float*)d_in[0];
    const float* W_ih = (const float*)d_in[1];
    const float* W_hh = (const float*)d_in[2];
    const float* b_ih = (const float*)d_in[3];
    const float* b_hh = (const float*)d_in[4];
    const float* W_fc = (const float*)d_in[5];
    const float* b_fc = (const float*)d_in[6];
    float* out = (float*)d_out;

    int B = in_sizes[0] / TSTEPS;  // x is [B, 512, 1]
    int rows_per_cta = WARPS_PER_CTA * ROWS_PER_WARP;
    int blocks = (B + rows_per_cta - 1) / rows_per_cta;
    lstm_kernel<<<blocks, 32 * WARPS_PER_CTA>>>(x, W_ih, W_hh, b_ih, b_hh, W_fc, b_fc, out, B);
}